// round 6
// baseline (speedup 1.0000x reference)
#include <cuda_runtime.h>
#include <math.h>
#include <stdint.h>

#define THREADS 256
#define TILE_ROWS 256
#define TILE_FLOATS (TILE_ROWS * 7)      // 1792
#define TILE_BYTES (TILE_FLOATS * 4)     // 7168
#define IN_STAGES 4
#define OUT_BUFS 2
#define MAX_BLOCKS 444                   // ~3 per SM on 148 SMs

struct Smem {
    float rep[IN_STAGES][TILE_FLOATS];
    float emo[IN_STAGES][TILE_FLOATS];
    float outb[OUT_BUFS][TILE_FLOATS];
    float M[56];                         // W_Q^T @ W_K, padded 7x8
    float CW[8];                         // colsum(W_D)[0..6], [7]=sum(b_D)
    unsigned long long full[IN_STAGES];
    unsigned long long empty[IN_STAGES];
};
#define SMEM_BYTES ((int)sizeof(Smem))

__device__ __forceinline__ void mbar_wait(uint32_t addr, int parity) {
    asm volatile(
        "{\n\t.reg .pred P;\n\t"
        "W_%=:\n\t"
        "mbarrier.try_wait.parity.acquire.cta.shared::cta.b64 P, [%0], %1;\n\t"
        "@!P bra W_%=;\n\t}"
        :: "r"(addr), "r"(parity) : "memory");
}

__device__ __forceinline__ void tma_in(uint32_t dst, const float* src, uint32_t mbar) {
    asm volatile("cp.async.bulk.shared::cluster.global.mbarrier::complete_tx::bytes "
                 "[%0], [%1], %2, [%3];"
                 :: "r"(dst), "l"(src), "r"(TILE_BYTES), "r"(mbar) : "memory");
}

__global__ __launch_bounds__(THREADS)
void emotion_kernel(const float* __restrict__ rep,
                    const float* __restrict__ emo,
                    const float* __restrict__ WQ,
                    const float* __restrict__ WK,
                    const float* __restrict__ WD,
                    const float* __restrict__ bD,
                    float* __restrict__ out,
                    int nrows)
{
    extern __shared__ __align__(16) char smem_raw[];
    Smem* sm = (Smem*)smem_raw;

    const int tid = threadIdx.x;
    const int bid = blockIdx.x;
    const int nblk = gridDim.x;
    const long long ntiles = ((long long)nrows + TILE_ROWS - 1) / TILE_ROWS;

    uint32_t a_full[IN_STAGES], a_empty[IN_STAGES], a_rep[IN_STAGES], a_emo[IN_STAGES];
    uint32_t a_out[OUT_BUFS];
    #pragma unroll
    for (int s = 0; s < IN_STAGES; ++s) {
        a_full[s]  = (uint32_t)__cvta_generic_to_shared(&sm->full[s]);
        a_empty[s] = (uint32_t)__cvta_generic_to_shared(&sm->empty[s]);
        a_rep[s]   = (uint32_t)__cvta_generic_to_shared(sm->rep[s]);
        a_emo[s]   = (uint32_t)__cvta_generic_to_shared(sm->emo[s]);
    }
    #pragma unroll
    for (int s = 0; s < OUT_BUFS; ++s)
        a_out[s] = (uint32_t)__cvta_generic_to_shared(sm->outb[s]);

    if (tid == 0) {
        #pragma unroll
        for (int s = 0; s < IN_STAGES; ++s) {
            asm volatile("mbarrier.init.shared::cta.b64 [%0], 1;"  :: "r"(a_full[s]) : "memory");
            asm volatile("mbarrier.init.shared::cta.b64 [%0], %1;" :: "r"(a_empty[s]), "r"(THREADS) : "memory");
        }
    }

    // per-block constants (tiny, L2-hit)
    if (tid < 49) {
        int j = tid / 7, k = tid % 7;
        float acc = 0.f;
        #pragma unroll
        for (int i = 0; i < 7; ++i) acc = fmaf(WQ[i * 7 + j], WK[i * 7 + k], acc);
        sm->M[j * 8 + k] = acc;
    } else if (tid < 56) {
        int k = tid - 49;
        float acc = 0.f;
        #pragma unroll
        for (int j = 0; j < 7; ++j) acc += WD[j * 7 + k];
        sm->CW[k] = acc;
    } else if (tid == 56) {
        float acc = 0.f;
        #pragma unroll
        for (int i = 0; i < 7; ++i) acc += bD[i];
        sm->CW[7] = acc;
    }
    __syncthreads();   // barriers + constants visible to all

    // ---- prologue: fill all IN_STAGES slots ----
    if (tid == 0) {
        #pragma unroll
        for (int s = 0; s < IN_STAGES; ++s) {
            long long tl = (long long)bid + (long long)s * nblk;
            if (tl < ntiles && (tl + 1) * TILE_ROWS <= (long long)nrows) {
                asm volatile("mbarrier.arrive.expect_tx.shared::cta.b64 _, [%0], %1;"
                             :: "r"(a_full[s]), "r"(2 * TILE_BYTES) : "memory");
                tma_in(a_rep[s], rep + tl * TILE_FLOATS, a_full[s]);
                tma_in(a_emo[s], emo + tl * TILE_FLOATS, a_full[s]);
            }
        }
    }

    const float4* sM4  = (const float4*)sm->M;
    const float4* sCW4 = (const float4*)sm->CW;

    int it = 0;
    for (long long tl = bid; tl < ntiles; tl += nblk, ++it) {
        const int s  = it & (IN_STAGES - 1);
        const int ph = (it / IN_STAGES) & 1;
        const int ob = it & (OUT_BUFS - 1);
        const long long row0 = tl * TILE_ROWS;
        const bool fulltile = (row0 + TILE_ROWS) <= (long long)nrows;

        if (fulltile) {
            mbar_wait(a_full[s], ph);

            const int base = tid * 7;
            float r[7], e[7];
            #pragma unroll
            for (int j = 0; j < 7; ++j) {
                r[j] = sm->rep[s][base + j];
                e[j] = sm->emo[s][base + j];
            }
            asm volatile("mbarrier.arrive.shared::cta.b64 _, [%0];" :: "r"(a_empty[s]) : "memory");

            // ---- refill this slot IMMEDIATELY (overlaps compute below) ----
            if (tid == 0) {
                long long tln = tl + (long long)IN_STAGES * nblk;
                if (tln < ntiles && (tln + 1) * TILE_ROWS <= (long long)nrows) {
                    mbar_wait(a_empty[s], ph);   // all 256 consumers drained
                    asm volatile("mbarrier.arrive.expect_tx.shared::cta.b64 _, [%0], %1;"
                                 :: "r"(a_full[s]), "r"(2 * TILE_BYTES) : "memory");
                    tma_in(a_rep[s], rep + tln * TILE_FLOATS, a_full[s]);
                    tma_in(a_emo[s], emo + tln * TILE_FLOATS, a_full[s]);
                }
            }

            // ---- compute (no max-subtraction: |raw| << 88, exp cannot overflow) ----
            float t[7];
            #pragma unroll
            for (int k = 0; k < 7; ++k) t[k] = 0.f;
            #pragma unroll
            for (int j = 0; j < 7; ++j) {
                float4 m0 = sM4[j * 2 + 0];
                float4 m1 = sM4[j * 2 + 1];
                float ej = e[j];
                t[0] = fmaf(ej, m0.x, t[0]);
                t[1] = fmaf(ej, m0.y, t[1]);
                t[2] = fmaf(ej, m0.z, t[2]);
                t[3] = fmaf(ej, m0.w, t[3]);
                t[4] = fmaf(ej, m1.x, t[4]);
                t[5] = fmaf(ej, m1.y, t[5]);
                t[6] = fmaf(ej, m1.z, t[6]);
            }
            float p[7], sum = 0.f;
            #pragma unroll
            for (int k = 0; k < 7; ++k) { p[k] = __expf(r[k] * t[k]); sum += p[k]; }
            float inv = __fdividef(1.f, sum);

            float4 c0 = sCW4[0];
            float4 c1 = sCW4[1];
            float cw[7] = {c0.x, c0.y, c0.z, c0.w, c1.x, c1.y, c1.z};
            float cb = c1.w;

            float o[7];
            #pragma unroll
            for (int k = 0; k < 7; ++k) {
                float sv = p[k] * inv;
                float s3 = sv * sv * sv;
                float d  = fmaf(s3, cw[k], cb);
                d = fminf(1.f, fmaxf(-1.f, d));
                o[k] = r[k] + d;
            }

            // gate out-buffer reuse: store from OUT_BUFS tiles ago must be done reading
            if (tid == 0) {
                asm volatile("cp.async.bulk.wait_group.read %0;" :: "n"(OUT_BUFS - 1) : "memory");
            }
            __syncthreads();

            #pragma unroll
            for (int j = 0; j < 7; ++j) sm->outb[ob][base + j] = o[j];

            asm volatile("fence.proxy.async.shared::cta;" ::: "memory");
            __syncthreads();

            if (tid == 0) {
                float* gdst = out + row0 * 7;
                asm volatile("cp.async.bulk.global.shared::cta.bulk_group [%0], [%1], %2;"
                             :: "l"(gdst), "r"(a_out[ob]), "r"(TILE_BYTES) : "memory");
                asm volatile("cp.async.bulk.commit_group;" ::: "memory");
            }
        } else {
            // partial tail tile: direct global path
            long long row = row0 + tid;
            if (row < (long long)nrows) {
                float r[7], e[7];
                #pragma unroll
                for (int j = 0; j < 7; ++j) {
                    r[j] = rep[row * 7 + j];
                    e[j] = emo[row * 7 + j];
                }
                float t[7];
                #pragma unroll
                for (int k = 0; k < 7; ++k) t[k] = 0.f;
                #pragma unroll
                for (int j = 0; j < 7; ++j) {
                    float ej = e[j];
                    #pragma unroll
                    for (int k = 0; k < 7; ++k)
                        t[k] = fmaf(ej, sm->M[j * 8 + k], t[k]);
                }
                float p[7], sum = 0.f;
                #pragma unroll
                for (int k = 0; k < 7; ++k) { p[k] = __expf(r[k] * t[k]); sum += p[k]; }
                float inv = __fdividef(1.f, sum);
                #pragma unroll
                for (int k = 0; k < 7; ++k) {
                    float sv = p[k] * inv;
                    float s3 = sv * sv * sv;
                    float d  = fmaf(s3, sm->CW[k], sm->CW[7]);
                    d = fminf(1.f, fmaxf(-1.f, d));
                    out[row * 7 + k] = r[k] + d;
                }
            }
        }
    }

    if (tid == 0) {
        asm volatile("cp.async.bulk.wait_group 0;" ::: "memory");
    }
}

extern "C" void kernel_launch(void* const* d_in, const int* in_sizes, int n_in,
                              void* d_out, int out_size)
{
    const float* rep = (const float*)d_in[0];
    const float* emo = (const float*)d_in[1];
    const float* WQ  = (const float*)d_in[2];
    const float* WK  = (const float*)d_in[3];
    const float* WD  = (const float*)d_in[4];
    const float* bD  = (const float*)d_in[5];
    float* out = (float*)d_out;

    int nrows = in_sizes[0] / 7;
    long long ntiles = ((long long)nrows + TILE_ROWS - 1) / TILE_ROWS;
    int grid = (int)((ntiles < MAX_BLOCKS) ? ntiles : MAX_BLOCKS);

    cudaFuncSetAttribute(emotion_kernel,
                         cudaFuncAttributeMaxDynamicSharedMemorySize, SMEM_BYTES);
    emotion_kernel<<<grid, THREADS, SMEM_BYTES>>>(rep, emo, WQ, WK, WD, bD, out, nrows);
}

// round 8
// speedup vs baseline: 1.2240x; 1.2240x over previous
#include <cuda_runtime.h>
#include <math.h>
#include <stdint.h>

#define THREADS 512
#define ROWS_PER_BLOCK 1024                     // 2 rows per thread
#define TILE_FLOATS (ROWS_PER_BLOCK * 7)        // 7168
#define TILE_BYTES (TILE_FLOATS * 4)            // 28672

struct Smem {
    float rep[TILE_FLOATS];                     // also reused as the output tile
    float emo[TILE_FLOATS];
    float M[56];                                // W_Q^T @ W_K, padded 7x8
    float CW[8];                                // colsum(W_D)[0..6], [7]=sum(b_D)
    unsigned long long mbar;
};
#define SMEM_BYTES ((int)sizeof(Smem))

__global__ __launch_bounds__(THREADS)
void emotion_kernel(const float* __restrict__ rep,
                    const float* __restrict__ emo,
                    const float* __restrict__ WQ,
                    const float* __restrict__ WK,
                    const float* __restrict__ WD,
                    const float* __restrict__ bD,
                    float* __restrict__ out,
                    int nrows)
{
    extern __shared__ __align__(16) char smem_raw[];
    Smem* sm = (Smem*)smem_raw;

    const int tid = threadIdx.x;
    const long long row0blk = (long long)blockIdx.x * ROWS_PER_BLOCK;
    const bool fullblk = (row0blk + ROWS_PER_BLOCK) <= (long long)nrows;

    const uint32_t a_mbar = (uint32_t)__cvta_generic_to_shared(&sm->mbar);
    const uint32_t a_rep  = (uint32_t)__cvta_generic_to_shared(sm->rep);
    const uint32_t a_emo  = (uint32_t)__cvta_generic_to_shared(sm->emo);

    if (tid == 0) {
        asm volatile("mbarrier.init.shared::cta.b64 [%0], 1;" :: "r"(a_mbar) : "memory");
    }
    __syncthreads();

    // ---- stage-in: two 28KB bulk TMA loads ----
    if (fullblk) {
        if (tid == 0) {
            asm volatile("mbarrier.arrive.expect_tx.shared::cta.b64 _, [%0], %1;"
                         :: "r"(a_mbar), "r"(2 * TILE_BYTES) : "memory");
            asm volatile("cp.async.bulk.shared::cluster.global.mbarrier::complete_tx::bytes "
                         "[%0], [%1], %2, [%3];"
                         :: "r"(a_rep), "l"(rep + row0blk * 7), "r"(TILE_BYTES), "r"(a_mbar) : "memory");
            asm volatile("cp.async.bulk.shared::cluster.global.mbarrier::complete_tx::bytes "
                         "[%0], [%1], %2, [%3];"
                         :: "r"(a_emo), "l"(emo + row0blk * 7), "r"(TILE_BYTES), "r"(a_mbar) : "memory");
        }
    } else {
        const long long total = (long long)nrows * 7;
        for (int s = tid; s < TILE_FLOATS; s += THREADS) {
            long long i = row0blk * 7 + s;
            if (i < total) { sm->rep[s] = rep[i]; sm->emo[s] = emo[i]; }
        }
    }

    // ---- per-block constants (overlap TMA; tiny L2-hit loads) ----
    if (tid < 49) {
        int j = tid / 7, k = tid % 7;
        float acc = 0.f;
        #pragma unroll
        for (int i = 0; i < 7; ++i) acc = fmaf(WQ[i * 7 + j], WK[i * 7 + k], acc);
        sm->M[j * 8 + k] = acc;
    } else if (tid < 56) {
        int k = tid - 49;
        float acc = 0.f;
        #pragma unroll
        for (int j = 0; j < 7; ++j) acc += WD[j * 7 + k];
        sm->CW[k] = acc;
    } else if (tid == 56) {
        float acc = 0.f;
        #pragma unroll
        for (int i = 0; i < 7; ++i) acc += bD[i];
        sm->CW[7] = acc;
    }
    __syncthreads();   // constants (and fallback staging) visible

    if (fullblk) {
        asm volatile(
            "{\n\t.reg .pred P;\n\t"
            "W_%=:\n\t"
            "mbarrier.try_wait.parity.acquire.cta.shared::cta.b64 P, [%0], 0;\n\t"
            "@!P bra W_%=;\n\t}"
            :: "r"(a_mbar) : "memory");
    }

    const float4* sM4  = (const float4*)sm->M;
    const float4* sCW4 = (const float4*)sm->CW;
    float4 c1 = sCW4[1];
    const float cb = c1.w;

    // ---- 2 rows per thread: rows tid and tid+512 (stride-7 LDS, conflict-free) ----
    #pragma unroll
    for (int rr = 0; rr < 2; ++rr) {
        const int rowloc = tid + rr * THREADS;
        const int base = rowloc * 7;
        const bool valid = (row0blk + rowloc) < (long long)nrows;

        float r[7], e[7];
        #pragma unroll
        for (int j = 0; j < 7; ++j) {
            r[j] = sm->rep[base + j];
            e[j] = sm->emo[base + j];
        }

        float o[7];
        if (valid) {
            float t[7];
            #pragma unroll
            for (int k = 0; k < 7; ++k) t[k] = 0.f;
            #pragma unroll
            for (int j = 0; j < 7; ++j) {
                float4 m0 = sM4[j * 2 + 0];
                float4 m1 = sM4[j * 2 + 1];
                float ej = e[j];
                t[0] = fmaf(ej, m0.x, t[0]);
                t[1] = fmaf(ej, m0.y, t[1]);
                t[2] = fmaf(ej, m0.z, t[2]);
                t[3] = fmaf(ej, m0.w, t[3]);
                t[4] = fmaf(ej, m1.x, t[4]);
                t[5] = fmaf(ej, m1.y, t[5]);
                t[6] = fmaf(ej, m1.z, t[6]);
            }
            // softmax without max-subtraction (|raw| << 88: exp is safe)
            float p[7], sum = 0.f;
            #pragma unroll
            for (int k = 0; k < 7; ++k) { p[k] = __expf(r[k] * t[k]); sum += p[k]; }
            float inv = __fdividef(1.f, sum);

            float4 c0 = sCW4[0];
            float cw[7] = {c0.x, c0.y, c0.z, c0.w, c1.x, c1.y, c1.z};
            #pragma unroll
            for (int k = 0; k < 7; ++k) {
                float sv = p[k] * inv;
                float s3 = sv * sv * sv;
                float d  = fmaf(s3, cw[k], cb);
                d = fminf(1.f, fmaxf(-1.f, d));
                o[k] = r[k] + d;
            }
        } else {
            #pragma unroll
            for (int k = 0; k < 7; ++k) o[k] = 0.f;
        }

        // write result in place into own rep slots (exclusive per thread)
        #pragma unroll
        for (int j = 0; j < 7; ++j) sm->rep[base + j] = o[j];
    }

    // ---- stage-out ----
    if (fullblk) {
        asm volatile("fence.proxy.async.shared::cta;" ::: "memory");
        __syncthreads();
        if (tid == 0) {
            asm volatile("cp.async.bulk.global.shared::cta.bulk_group [%0], [%1], %2;"
                         :: "l"(out + row0blk * 7), "r"(a_rep), "r"(TILE_BYTES) : "memory");
            asm volatile("cp.async.bulk.commit_group;" ::: "memory");
            asm volatile("cp.async.bulk.wait_group.read 0;" ::: "memory");
        }
    } else {
        __syncthreads();
        const long long total = (long long)nrows * 7;
        for (int s = tid; s < TILE_FLOATS; s += THREADS) {
            long long i = row0blk * 7 + s;
            if (i < total) out[i] = sm->rep[s];
        }
    }
}

extern "C" void kernel_launch(void* const* d_in, const int* in_sizes, int n_in,
                              void* d_out, int out_size)
{
    const float* rep = (const float*)d_in[0];
    const float* emo = (const float*)d_in[1];
    const float* WQ  = (const float*)d_in[2];
    const float* WK  = (const float*)d_in[3];
    const float* WD  = (const float*)d_in[4];
    const float* bD  = (const float*)d_in[5];
    float* out = (float*)d_out;

    int nrows = in_sizes[0] / 7;
    int grid  = (nrows + ROWS_PER_BLOCK - 1) / ROWS_PER_BLOCK;

    cudaFuncSetAttribute(emotion_kernel,
                         cudaFuncAttributeMaxDynamicSharedMemorySize, SMEM_BYTES);
    emotion_kernel<<<grid, THREADS, SMEM_BYTES>>>(rep, emo, WQ, WK, WD, bD, out, nrows);
}